// round 3
// baseline (speedup 1.0000x reference)
#include <cuda_runtime.h>
#include <cuda_bf16.h>

// ---------------- problem constants ----------------
#define NN 131072
#define EE 524288
#define DD 100
#define TD 300
#define DA 50
#define DC 30
#define ND (NN*DD)          // 13,107,200

// ---------------- scratch (static device globals; no allocation) ----------------
__device__ float g_h[ND];
__device__ float g_fm[ND];
__device__ float g_msg[ND];

// ---------------- f32x2 packed-FMA helpers (sm_103a FFMA2 path) ----------------
typedef unsigned long long u64;

__device__ __forceinline__ u64 ffma2(u64 a, u64 b, u64 c) {
    u64 d;
    asm("fma.rn.f32x2 %0, %1, %2, %3;" : "=l"(d) : "l"(a), "l"(b), "l"(c));
    return d;
}
__device__ __forceinline__ u64 dup2(float x) {
    u64 d;
    asm("mov.b64 %0, {%1, %1};" : "=l"(d) : "f"(x));
    return d;
}
__device__ __forceinline__ u64 pk2(float a, float b) {
    u64 d;
    asm("mov.b64 %0, {%1, %2};" : "=l"(d) : "f"(a), "f"(b));
    return d;
}
__device__ __forceinline__ float2 unpk(u64 a) {
    float2 r;
    asm("mov.b64 {%0, %1}, %2;" : "=f"(r.x), "=f"(r.y) : "l"(a));
    return r;
}
__device__ __forceinline__ float sigf(float v) {
    return 1.0f / (1.0f + __expf(-v));
}

// ---------------- init: h = features @ init_W + init_b ----------------
__global__ void init_kernel(const float* __restrict__ feat,
                            const float* __restrict__ W,   // [4, D]
                            const float* __restrict__ b) {
    int i = blockIdx.x * blockDim.x + threadIdx.x;
    if (i >= ND) return;
    int n = i / DD;
    int d = i - n * DD;
    float f0 = feat[n * 4 + 0], f1 = feat[n * 4 + 1];
    float f2 = feat[n * 4 + 2], f3 = feat[n * 4 + 3];
    g_h[i] = b[d] + f0 * W[d] + f1 * W[DD + d] + f2 * W[2 * DD + d] + f3 * W[3 * DD + d];
}

// ---------------- zero msg buffer ----------------
__global__ void zero_kernel() {
    int i = blockIdx.x * blockDim.x + threadIdx.x;   // ND/4 threads
    ((float4*)g_msg)[i] = make_float4(0.f, 0.f, 0.f, 0.f);
}

// ---------------- fused 2-layer message MLP: g_fm = relu(g_h@W1+b1)@W2+b2 ----------------
#define MLP_NODES 64
#define MLP_THREADS 512
#define MLP_SMEM_FLOATS (5000 + 5000 + MLP_NODES*DD + MLP_NODES*DA + DD + 64)
// layout: s_w1[5000] s_w2[5000] s_h[6400] s_hid[3200] s_b2[100](16B aligned) s_b1[50..]

__global__ void __launch_bounds__(MLP_THREADS, 2)
mlp_kernel(const float* __restrict__ W1, const float* __restrict__ b1,
           const float* __restrict__ W2, const float* __restrict__ b2) {
    extern __shared__ float smem[];
    float* s_w1 = smem;
    float* s_w2 = s_w1 + 5000;
    float* s_h  = s_w2 + 5000;
    float* s_hid = s_h + MLP_NODES * DD;
    float* s_b2 = s_hid + MLP_NODES * DA;
    float* s_b1 = s_b2 + DD;

    int tid = threadIdx.x;
    int base = blockIdx.x * MLP_NODES;

    for (int i = tid; i < 5000; i += MLP_THREADS) { s_w1[i] = W1[i]; s_w2[i] = W2[i]; }
    for (int i = tid; i < MLP_NODES * DD; i += MLP_THREADS) s_h[i] = g_h[base * DD + i];
    if (tid < DD) s_b2[tid] = b2[tid];
    if (tid < DA) s_b1[tid] = b1[tid];
    __syncthreads();

    int warp = tid >> 5, lane = tid & 31;
    int nb = warp * 4;
    bool act = lane < 25;

    // layer 1: hidden[j0], hidden[j0+1], j0 = 2*lane
    if (act) {
        int j0 = 2 * lane;
        u64 bias = pk2(s_b1[j0], s_b1[j0 + 1]);
        u64 acc[4] = {bias, bias, bias, bias};
        const float* x0 = &s_h[(nb + 0) * DD];
        const float* x1 = &s_h[(nb + 1) * DD];
        const float* x2 = &s_h[(nb + 2) * DD];
        const float* x3 = &s_h[(nb + 3) * DD];
#pragma unroll 4
        for (int d = 0; d < DD; d++) {
            u64 w = *(const u64*)&s_w1[d * DA + j0];
            acc[0] = ffma2(w, dup2(x0[d]), acc[0]);
            acc[1] = ffma2(w, dup2(x1[d]), acc[1]);
            acc[2] = ffma2(w, dup2(x2[d]), acc[2]);
            acc[3] = ffma2(w, dup2(x3[d]), acc[3]);
        }
#pragma unroll
        for (int nn = 0; nn < 4; nn++) {
            float2 v = unpk(acc[nn]);
            float2 o = make_float2(fmaxf(v.x, 0.f), fmaxf(v.y, 0.f));
            *(float2*)&s_hid[(nb + nn) * DA + j0] = o;
        }
    }
    __syncwarp();

    // layer 2: out[k0..k0+3], k0 = 4*lane
    if (act) {
        int k0 = 4 * lane;
        float4 bb = *(const float4*)&s_b2[k0];
        u64 b0 = pk2(bb.x, bb.y), b1p = pk2(bb.z, bb.w);
        u64 a[4][2];
#pragma unroll
        for (int nn = 0; nn < 4; nn++) { a[nn][0] = b0; a[nn][1] = b1p; }
        const float* h0 = &s_hid[(nb + 0) * DA];
        const float* h1 = &s_hid[(nb + 1) * DA];
        const float* h2 = &s_hid[(nb + 2) * DA];
        const float* h3 = &s_hid[(nb + 3) * DA];
#pragma unroll 4
        for (int j = 0; j < DA; j++) {
            ulonglong2 w = *(const ulonglong2*)&s_w2[j * DD + k0];
            u64 v0 = dup2(h0[j]), v1 = dup2(h1[j]), v2 = dup2(h2[j]), v3 = dup2(h3[j]);
            a[0][0] = ffma2(w.x, v0, a[0][0]); a[0][1] = ffma2(w.y, v0, a[0][1]);
            a[1][0] = ffma2(w.x, v1, a[1][0]); a[1][1] = ffma2(w.y, v1, a[1][1]);
            a[2][0] = ffma2(w.x, v2, a[2][0]); a[2][1] = ffma2(w.y, v2, a[2][1]);
            a[3][0] = ffma2(w.x, v3, a[3][0]); a[3][1] = ffma2(w.y, v3, a[3][1]);
        }
#pragma unroll
        for (int nn = 0; nn < 4; nn++) {
            float2 p0 = unpk(a[nn][0]), p1 = unpk(a[nn][1]);
            float4 o = make_float4(p0.x, p0.y, p1.x, p1.y);
            *(float4*)&g_fm[(base + nb + nn) * DD + k0] = o;
        }
    }
}

// ---------------- edge scatter: msg[dst] += fm[src] ----------------
__global__ void scatter_kernel(const int* __restrict__ src_idx,
                               const int* __restrict__ dst_idx) {
    int warp = (blockIdx.x * blockDim.x + threadIdx.x) >> 5;
    int lane = threadIdx.x & 31;
    if (warp >= EE || lane >= 25) return;
    int s = src_idx[warp];
    int t = dst_idx[warp];
    float4 v = *(const float4*)&g_fm[s * DD + 4 * lane];
    float* p = &g_msg[t * DD + 4 * lane];
    atomicAdd(p + 0, v.x);
    atomicAdd(p + 1, v.y);
    atomicAdd(p + 2, v.z);
    atomicAdd(p + 3, v.w);
}

// ---------------- fused GRU step: g_h = GRU(g_msg, g_h) ----------------
#define GRU_NODES 64
#define GRU_THREADS 512
#define GRU_SMEM_FLOATS (30000 + GRU_NODES*TD + GRU_NODES*DD + 600)
// layout: s_w[30000] s_gi[19200] s_xh[6400] s_bi[300] s_bh[300]  -> 224,800 B

__global__ void __launch_bounds__(GRU_THREADS, 1)
gru_kernel(const float* __restrict__ Wih, const float* __restrict__ Whh,
           const float* __restrict__ bih, const float* __restrict__ bhh) {
    extern __shared__ float smem[];
    float* s_w  = smem;
    float* s_gi = s_w + 30000;
    float* s_xh = s_gi + GRU_NODES * TD;
    float* s_bi = s_xh + GRU_NODES * DD;
    float* s_bh = s_bi + TD;

    int tid = threadIdx.x;
    int base = blockIdx.x * GRU_NODES;
    int warp = tid >> 5, lane = tid & 31;
    int nb = warp * 4;
    int k0 = 4 * lane;
    bool act = lane < 25;

    // ---- phase 1: load Wih^T (transposed on the fly) + x rows + biases ----
    for (int i = tid; i < 30000; i += GRU_THREADS) {
        int j = i / DD, d = i - j * DD;
        s_w[d * TD + j] = Wih[i];
    }
    for (int i = tid; i < GRU_NODES * DD; i += GRU_THREADS) s_xh[i] = g_msg[base * DD + i];
    if (tid < TD) { s_bi[tid] = bih[tid]; s_bh[tid] = bhh[tid]; }
    __syncthreads();

    if (act) {
        float4 br = *(const float4*)&s_bi[k0];
        float4 bz = *(const float4*)&s_bi[DD + k0];
        float4 bn = *(const float4*)&s_bi[2 * DD + k0];
        u64 aR[4][2], aZ[4][2], aN[4][2];
#pragma unroll
        for (int nn = 0; nn < 4; nn++) {
            aR[nn][0] = pk2(br.x, br.y); aR[nn][1] = pk2(br.z, br.w);
            aZ[nn][0] = pk2(bz.x, bz.y); aZ[nn][1] = pk2(bz.z, bz.w);
            aN[nn][0] = pk2(bn.x, bn.y); aN[nn][1] = pk2(bn.z, bn.w);
        }
        const float* x0 = &s_xh[(nb + 0) * DD];
        const float* x1 = &s_xh[(nb + 1) * DD];
        const float* x2 = &s_xh[(nb + 2) * DD];
        const float* x3 = &s_xh[(nb + 3) * DD];
#pragma unroll 2
        for (int d = 0; d < DD; d++) {
            const float* wrow = s_w + d * TD + k0;
            ulonglong2 wr = *(const ulonglong2*)(wrow);
            ulonglong2 wz = *(const ulonglong2*)(wrow + DD);
            ulonglong2 wn = *(const ulonglong2*)(wrow + 2 * DD);
            u64 v0 = dup2(x0[d]), v1 = dup2(x1[d]), v2 = dup2(x2[d]), v3 = dup2(x3[d]);
            aR[0][0] = ffma2(wr.x, v0, aR[0][0]); aR[0][1] = ffma2(wr.y, v0, aR[0][1]);
            aZ[0][0] = ffma2(wz.x, v0, aZ[0][0]); aZ[0][1] = ffma2(wz.y, v0, aZ[0][1]);
            aN[0][0] = ffma2(wn.x, v0, aN[0][0]); aN[0][1] = ffma2(wn.y, v0, aN[0][1]);
            aR[1][0] = ffma2(wr.x, v1, aR[1][0]); aR[1][1] = ffma2(wr.y, v1, aR[1][1]);
            aZ[1][0] = ffma2(wz.x, v1, aZ[1][0]); aZ[1][1] = ffma2(wz.y, v1, aZ[1][1]);
            aN[1][0] = ffma2(wn.x, v1, aN[1][0]); aN[1][1] = ffma2(wn.y, v1, aN[1][1]);
            aR[2][0] = ffma2(wr.x, v2, aR[2][0]); aR[2][1] = ffma2(wr.y, v2, aR[2][1]);
            aZ[2][0] = ffma2(wz.x, v2, aZ[2][0]); aZ[2][1] = ffma2(wz.y, v2, aZ[2][1]);
            aN[2][0] = ffma2(wn.x, v2, aN[2][0]); aN[2][1] = ffma2(wn.y, v2, aN[2][1]);
            aR[3][0] = ffma2(wr.x, v3, aR[3][0]); aR[3][1] = ffma2(wr.y, v3, aR[3][1]);
            aZ[3][0] = ffma2(wz.x, v3, aZ[3][0]); aZ[3][1] = ffma2(wz.y, v3, aZ[3][1]);
            aN[3][0] = ffma2(wn.x, v3, aN[3][0]); aN[3][1] = ffma2(wn.y, v3, aN[3][1]);
        }
#pragma unroll
        for (int nn = 0; nn < 4; nn++) {
            float* gbase = &s_gi[(nb + nn) * TD];
            *(ulonglong2*)&gbase[k0]          = make_ulonglong2(aR[nn][0], aR[nn][1]);
            *(ulonglong2*)&gbase[DD + k0]     = make_ulonglong2(aZ[nn][0], aZ[nn][1]);
            *(ulonglong2*)&gbase[2 * DD + k0] = make_ulonglong2(aN[nn][0], aN[nn][1]);
        }
    }
    __syncthreads();

    // ---- phase 2: load Whh^T + h rows ----
    for (int i = tid; i < 30000; i += GRU_THREADS) {
        int j = i / DD, d = i - j * DD;
        s_w[d * TD + j] = Whh[i];
    }
    for (int i = tid; i < GRU_NODES * DD; i += GRU_THREADS) s_xh[i] = g_h[base * DD + i];
    __syncthreads();

    if (act) {
        float4 br = *(const float4*)&s_bh[k0];
        float4 bz = *(const float4*)&s_bh[DD + k0];
        float4 bn = *(const float4*)&s_bh[2 * DD + k0];
        u64 aR[4][2], aZ[4][2], aN[4][2];
#pragma unroll
        for (int nn = 0; nn < 4; nn++) {
            aR[nn][0] = pk2(br.x, br.y); aR[nn][1] = pk2(br.z, br.w);
            aZ[nn][0] = pk2(bz.x, bz.y); aZ[nn][1] = pk2(bz.z, bz.w);
            aN[nn][0] = pk2(bn.x, bn.y); aN[nn][1] = pk2(bn.z, bn.w);
        }
        const float* h0 = &s_xh[(nb + 0) * DD];
        const float* h1 = &s_xh[(nb + 1) * DD];
        const float* h2 = &s_xh[(nb + 2) * DD];
        const float* h3 = &s_xh[(nb + 3) * DD];
#pragma unroll 2
        for (int d = 0; d < DD; d++) {
            const float* wrow = s_w + d * TD + k0;
            ulonglong2 wr = *(const ulonglong2*)(wrow);
            ulonglong2 wz = *(const ulonglong2*)(wrow + DD);
            ulonglong2 wn = *(const ulonglong2*)(wrow + 2 * DD);
            u64 v0 = dup2(h0[d]), v1 = dup2(h1[d]), v2 = dup2(h2[d]), v3 = dup2(h3[d]);
            aR[0][0] = ffma2(wr.x, v0, aR[0][0]); aR[0][1] = ffma2(wr.y, v0, aR[0][1]);
            aZ[0][0] = ffma2(wz.x, v0, aZ[0][0]); aZ[0][1] = ffma2(wz.y, v0, aZ[0][1]);
            aN[0][0] = ffma2(wn.x, v0, aN[0][0]); aN[0][1] = ffma2(wn.y, v0, aN[0][1]);
            aR[1][0] = ffma2(wr.x, v1, aR[1][0]); aR[1][1] = ffma2(wr.y, v1, aR[1][1]);
            aZ[1][0] = ffma2(wz.x, v1, aZ[1][0]); aZ[1][1] = ffma2(wz.y, v1, aZ[1][1]);
            aN[1][0] = ffma2(wn.x, v1, aN[1][0]); aN[1][1] = ffma2(wn.y, v1, aN[1][1]);
            aR[2][0] = ffma2(wr.x, v2, aR[2][0]); aR[2][1] = ffma2(wr.y, v2, aR[2][1]);
            aZ[2][0] = ffma2(wz.x, v2, aZ[2][0]); aZ[2][1] = ffma2(wz.y, v2, aZ[2][1]);
            aN[2][0] = ffma2(wn.x, v2, aN[2][0]); aN[2][1] = ffma2(wn.y, v2, aN[2][1]);
            aR[3][0] = ffma2(wr.x, v3, aR[3][0]); aR[3][1] = ffma2(wr.y, v3, aR[3][1]);
            aZ[3][0] = ffma2(wz.x, v3, aZ[3][0]); aZ[3][1] = ffma2(wz.y, v3, aZ[3][1]);
            aN[3][0] = ffma2(wn.x, v3, aN[3][0]); aN[3][1] = ffma2(wn.y, v3, aN[3][1]);
        }
        // gate fusion + state update
#pragma unroll
        for (int nn = 0; nn < 4; nn++) {
            float2 hr0 = unpk(aR[nn][0]), hr1 = unpk(aR[nn][1]);
            float2 hz0 = unpk(aZ[nn][0]), hz1 = unpk(aZ[nn][1]);
            float2 hn0 = unpk(aN[nn][0]), hn1 = unpk(aN[nn][1]);
            const float* gbase = &s_gi[(nb + nn) * TD];
            float4 gr = *(const float4*)&gbase[k0];
            float4 gz = *(const float4*)&gbase[DD + k0];
            float4 gn = *(const float4*)&gbase[2 * DD + k0];
            float4 hp = *(const float4*)&s_xh[(nb + nn) * DD + k0];

            float r0 = sigf(gr.x + hr0.x), r1 = sigf(gr.y + hr0.y);
            float r2 = sigf(gr.z + hr1.x), r3 = sigf(gr.w + hr1.y);
            float z0 = sigf(gz.x + hz0.x), z1 = sigf(gz.y + hz0.y);
            float z2 = sigf(gz.z + hz1.x), z3 = sigf(gz.w + hz1.y);
            float n0 = tanhf(gn.x + r0 * hn0.x), n1 = tanhf(gn.y + r1 * hn0.y);
            float n2 = tanhf(gn.z + r2 * hn1.x), n3 = tanhf(gn.w + r3 * hn1.y);
            float4 o;
            o.x = (1.f - z0) * n0 + z0 * hp.x;
            o.y = (1.f - z1) * n1 + z1 * hp.y;
            o.z = (1.f - z2) * n2 + z2 * hp.z;
            o.w = (1.f - z3) * n3 + z3 * hp.w;
            *(float4*)&g_h[(base + nb + nn) * DD + k0] = o;
        }
    }
}

// ---------------- classifier: out = relu(h@W1+b1)@W2+b2 ----------------
__global__ void cls_kernel(const float* __restrict__ W1, const float* __restrict__ b1,
                           const float* __restrict__ W2, const float* __restrict__ b2,
                           float* __restrict__ out) {
    __shared__ float s_w1[DD * DC];
    __shared__ float s_b1[DC];
    __shared__ float s_w2[DC];
    __shared__ float s_row[8 * DD];

    int tid = threadIdx.x;
    int warp = tid >> 5, lane = tid & 31;
    int node = blockIdx.x * 8 + warp;

    for (int i = tid; i < DD * DC; i += blockDim.x) s_w1[i] = W1[i];
    if (tid < DC) { s_b1[tid] = b1[tid]; s_w2[tid] = W2[tid]; }
    __syncthreads();

    const float* hrow = &g_h[node * DD];
    float* rbuf = &s_row[warp * DD];
    rbuf[lane] = hrow[lane];
    rbuf[lane + 32] = hrow[lane + 32];
    rbuf[lane + 64] = hrow[lane + 64];
    if (lane < 4) rbuf[lane + 96] = hrow[lane + 96];
    __syncwarp();

    float v = 0.f;
    if (lane < DC) {
        float acc = s_b1[lane];
#pragma unroll 4
        for (int d = 0; d < DD; d++) acc += rbuf[d] * s_w1[d * DC + lane];
        v = fmaxf(acc, 0.f) * s_w2[lane];
    }
#pragma unroll
    for (int off = 16; off > 0; off >>= 1) v += __shfl_down_sync(0xFFFFFFFFu, v, off);
    if (lane == 0) out[node] = v + b2[0];
}

// ---------------- host launch ----------------
extern "C" void kernel_launch(void* const* d_in, const int* in_sizes, int n_in,
                              void* d_out, int out_size) {
    const float* features = (const float*)d_in[0];
    const int* edge_row   = (const int*)d_in[1];
    const int* edge_col   = (const int*)d_in[2];
    const float* init_W = (const float*)d_in[3];
    const float* init_b = (const float*)d_in[4];
    const float* fmsg_W1 = (const float*)d_in[5];
    const float* fmsg_b1 = (const float*)d_in[6];
    const float* fmsg_W2 = (const float*)d_in[7];
    const float* fmsg_b2 = (const float*)d_in[8];
    const float* bmsg_W1 = (const float*)d_in[9];
    const float* bmsg_b1 = (const float*)d_in[10];
    const float* bmsg_W2 = (const float*)d_in[11];
    const float* bmsg_b2 = (const float*)d_in[12];
    const float* fgru_Wih = (const float*)d_in[13];
    const float* fgru_Whh = (const float*)d_in[14];
    const float* fgru_bih = (const float*)d_in[15];
    const float* fgru_bhh = (const float*)d_in[16];
    const float* bgru_Wih = (const float*)d_in[17];
    const float* bgru_Whh = (const float*)d_in[18];
    const float* bgru_bih = (const float*)d_in[19];
    const float* bgru_bhh = (const float*)d_in[20];
    const float* cls_W1 = (const float*)d_in[21];
    const float* cls_b1 = (const float*)d_in[22];
    const float* cls_W2 = (const float*)d_in[23];
    const float* cls_b2 = (const float*)d_in[24];
    float* out = (float*)d_out;

    const int mlp_smem = MLP_SMEM_FLOATS * 4;
    const int gru_smem = GRU_SMEM_FLOATS * 4;
    cudaFuncSetAttribute((const void*)mlp_kernel,
                         cudaFuncAttributeMaxDynamicSharedMemorySize, mlp_smem);
    cudaFuncSetAttribute((const void*)gru_kernel,
                         cudaFuncAttributeMaxDynamicSharedMemorySize, gru_smem);

    init_kernel<<<(ND + 255) / 256, 256>>>(features, init_W, init_b);

    const int mlp_blocks = NN / MLP_NODES;      // 2048
    const int gru_blocks = NN / GRU_NODES;      // 2048
    const int zero_blocks = (ND / 4) / 256;     // 12800
    const int scat_blocks = EE / 8;             // 65536 (8 warps/block, warp per edge)

    for (int r = 0; r < 20; r++) {
        // forward pass
        mlp_kernel<<<mlp_blocks, MLP_THREADS, mlp_smem>>>(fmsg_W1, fmsg_b1, fmsg_W2, fmsg_b2);
        zero_kernel<<<zero_blocks, 256>>>();
        scatter_kernel<<<scat_blocks, 256>>>(edge_col, edge_row);   // msg[row] += fm[col]
        gru_kernel<<<gru_blocks, GRU_THREADS, gru_smem>>>(fgru_Wih, fgru_Whh, fgru_bih, fgru_bhh);
        // backward pass
        mlp_kernel<<<mlp_blocks, MLP_THREADS, mlp_smem>>>(bmsg_W1, bmsg_b1, bmsg_W2, bmsg_b2);
        zero_kernel<<<zero_blocks, 256>>>();
        scatter_kernel<<<scat_blocks, 256>>>(edge_row, edge_col);   // msg[col] += bm[row]
        gru_kernel<<<gru_blocks, GRU_THREADS, gru_smem>>>(bgru_Wih, bgru_Whh, bgru_bih, bgru_bhh);
    }

    cls_kernel<<<NN / 8, 256>>>(cls_W1, cls_b1, cls_W2, cls_b2, out);
    (void)in_sizes; (void)n_in; (void)out_size;
}

// round 4
// speedup vs baseline: 1.1376x; 1.1376x over previous
#include <cuda_runtime.h>
#include <cuda_bf16.h>

// ---------------- problem constants ----------------
#define NN 131072
#define EE 524288
#define DD 100
#define TD 300
#define DA 50
#define DC 30
#define ND (NN*DD)          // 13,107,200

// ---------------- scratch (static device globals; no allocation) ----------------
__device__ float g_h[ND];
__device__ float g_fm[ND];
__device__ float g_msg[ND];
__device__ float g_WT[4][30000];   // pre-transposed [d][j] GRU weights: fWih,fWhh,bWih,bWhh

// ---------------- f32x2 packed-FMA helpers (sm_103a FFMA2 path) ----------------
typedef unsigned long long u64;

__device__ __forceinline__ u64 ffma2(u64 a, u64 b, u64 c) {
    u64 d;
    asm("fma.rn.f32x2 %0, %1, %2, %3;" : "=l"(d) : "l"(a), "l"(b), "l"(c));
    return d;
}
__device__ __forceinline__ u64 dup2(float x) {
    u64 d;
    asm("mov.b64 %0, {%1, %1};" : "=l"(d) : "f"(x));
    return d;
}
__device__ __forceinline__ u64 pk2(float a, float b) {
    u64 d;
    asm("mov.b64 %0, {%1, %2};" : "=l"(d) : "f"(a), "f"(b));
    return d;
}
__device__ __forceinline__ float2 unpk(u64 a) {
    float2 r;
    asm("mov.b64 {%0, %1}, %2;" : "=f"(r.x), "=f"(r.y) : "l"(a));
    return r;
}
__device__ __forceinline__ float sigf(float v) {
    return 1.0f / (1.0f + __expf(-v));
}

// ---------------- init: h = features @ init_W + init_b ----------------
__global__ void init_kernel(const float* __restrict__ feat,
                            const float* __restrict__ W,   // [4, D]
                            const float* __restrict__ b) {
    int i = blockIdx.x * blockDim.x + threadIdx.x;
    if (i >= ND) return;
    int n = i / DD;
    int d = i - n * DD;
    float f0 = feat[n * 4 + 0], f1 = feat[n * 4 + 1];
    float f2 = feat[n * 4 + 2], f3 = feat[n * 4 + 3];
    g_h[i] = b[d] + f0 * W[d] + f1 * W[DD + d] + f2 * W[2 * DD + d] + f3 * W[3 * DD + d];
}

// ---------------- one-time weight transpose: g_WT[m][d*300+j] = W[j*100+d] ----------------
__global__ void transpose_w_kernel(const float* __restrict__ A, const float* __restrict__ B,
                                   const float* __restrict__ C, const float* __restrict__ E) {
    int i = blockIdx.x * blockDim.x + threadIdx.x;
    if (i >= 30000) return;
    int d = i / TD, j = i - d * TD;
    int src = j * DD + d;
    g_WT[0][i] = A[src];
    g_WT[1][i] = B[src];
    g_WT[2][i] = C[src];
    g_WT[3][i] = E[src];
}

// ---------------- zero msg buffer ----------------
__global__ void zero_kernel() {
    int i = blockIdx.x * blockDim.x + threadIdx.x;   // ND/4 threads
    ((float4*)g_msg)[i] = make_float4(0.f, 0.f, 0.f, 0.f);
}

// ---------------- fused 2-layer message MLP (8 nodes/warp) ----------------
#define MLP_THREADS 256
#define MLP_NODES 64
#define MLP_SMEM_FLOATS (5000 + 5000 + MLP_NODES*DD + MLP_NODES*DA + DD + 52)
// s_w1[0,5000) s_w2[5000,10000) s_h[10000,16400) s_hid[16400,19600) s_b2[19600,19700) s_b1[19700,...)

__global__ void __launch_bounds__(MLP_THREADS, 2)
mlp_kernel(const float* __restrict__ W1, const float* __restrict__ b1,
           const float* __restrict__ W2, const float* __restrict__ b2) {
    extern __shared__ float smem[];
    float* s_w1 = smem;
    float* s_w2 = s_w1 + 5000;
    float* s_h  = s_w2 + 5000;
    float* s_hid = s_h + MLP_NODES * DD;
    float* s_b2 = s_hid + MLP_NODES * DA;
    float* s_b1 = s_b2 + DD;

    int tid = threadIdx.x;
    int base = blockIdx.x * MLP_NODES;

    for (int i = tid; i < 5000; i += MLP_THREADS) { s_w1[i] = W1[i]; s_w2[i] = W2[i]; }
    for (int i = tid; i < MLP_NODES * DD / 4; i += MLP_THREADS)
        ((float4*)s_h)[i] = ((const float4*)g_h)[base * (DD / 4) + i];
    if (tid < DD) s_b2[tid] = b2[tid];
    if (tid < DA) s_b1[tid] = b1[tid];
    __syncthreads();

    int warp = tid >> 5, lane = tid & 31;
    int nb = warp * 8;
    int k0 = 4 * lane;
    bool act = lane < 25;

    // layer 1: hidden[j0], hidden[j0+1], j0 = 2*lane, 8 nodes per warp
    if (act) {
        int j0 = 2 * lane;
        u64 bias = pk2(s_b1[j0], s_b1[j0 + 1]);
        u64 acc[8];
#pragma unroll
        for (int nn = 0; nn < 8; nn++) acc[nn] = bias;
        const float* xp = s_h + nb * DD;
#pragma unroll 2
        for (int d = 0; d < DD; d++) {
            u64 w = *(const u64*)&s_w1[d * DA + j0];
#pragma unroll
            for (int nn = 0; nn < 8; nn++)
                acc[nn] = ffma2(w, dup2(xp[nn * DD + d]), acc[nn]);
        }
#pragma unroll
        for (int nn = 0; nn < 8; nn++) {
            float2 v = unpk(acc[nn]);
            *(float2*)&s_hid[(nb + nn) * DA + j0] =
                make_float2(fmaxf(v.x, 0.f), fmaxf(v.y, 0.f));
        }
    }
    __syncwarp();

    // layer 2: out[k0..k0+3], 8 nodes per warp
    if (act) {
        float4 bb = *(const float4*)&s_b2[k0];
        u64 b0 = pk2(bb.x, bb.y), b1p = pk2(bb.z, bb.w);
        u64 a[8][2];
#pragma unroll
        for (int nn = 0; nn < 8; nn++) { a[nn][0] = b0; a[nn][1] = b1p; }
        const float* hp = s_hid + nb * DA;
#pragma unroll 2
        for (int j = 0; j < DA; j++) {
            ulonglong2 w = *(const ulonglong2*)&s_w2[j * DD + k0];
#pragma unroll
            for (int nn = 0; nn < 8; nn++) {
                u64 v = dup2(hp[nn * DA + j]);
                a[nn][0] = ffma2(w.x, v, a[nn][0]);
                a[nn][1] = ffma2(w.y, v, a[nn][1]);
            }
        }
#pragma unroll
        for (int nn = 0; nn < 8; nn++) {
            float2 p0 = unpk(a[nn][0]), p1 = unpk(a[nn][1]);
            *(float4*)&g_fm[(base + nb + nn) * DD + k0] =
                make_float4(p0.x, p0.y, p1.x, p1.y);
        }
    }
}

// ---------------- edge scatter: msg[dst] += fm[src] (vector RED) ----------------
__global__ void scatter_kernel(const int* __restrict__ src_idx,
                               const int* __restrict__ dst_idx) {
    int warp = (blockIdx.x * blockDim.x + threadIdx.x) >> 5;
    int lane = threadIdx.x & 31;
    if (lane >= 25) return;
    int s = src_idx[warp];
    int t = dst_idx[warp];
    float4 v = *(const float4*)&g_fm[s * DD + 4 * lane];
    float* p = &g_msg[t * DD + 4 * lane];
    asm volatile("red.global.add.v4.f32 [%0], {%1, %2, %3, %4};"
                 :: "l"(p), "f"(v.x), "f"(v.y), "f"(v.z), "f"(v.w) : "memory");
}

// ---------------- fused GRU step: g_h = GRU(g_msg, g_h), 8 nodes/warp ----------------
#define GRU_THREADS 256
#define GRU_NODES 64
#define GRU_SMEM_FLOATS (30000 + GRU_NODES*TD + GRU_NODES*DD + 300 + 300)
// s_w[30000] s_gi[19200] s_x[6400] s_bi[300] s_bh[300] -> 224,800 B

__global__ void __launch_bounds__(GRU_THREADS, 1)
gru_kernel(const float* __restrict__ WTih, const float* __restrict__ WThh,
           const float* __restrict__ bih, const float* __restrict__ bhh) {
    extern __shared__ float smem[];
    float* s_w  = smem;
    float* s_gi = s_w + 30000;
    float* s_x  = s_gi + GRU_NODES * TD;
    float* s_bi = s_x + GRU_NODES * DD;
    float* s_bh = s_bi + TD;

    int tid = threadIdx.x;
    int base = blockIdx.x * GRU_NODES;
    int warp = tid >> 5, lane = tid & 31;
    int nb = warp * 8;
    int k0 = 4 * lane;
    bool act = lane < 25;

    // ---- phase 1: coalesced copy of pre-transposed Wih + msg tile + biases ----
    for (int i = tid; i < 7500; i += GRU_THREADS)
        ((float4*)s_w)[i] = ((const float4*)WTih)[i];
    for (int i = tid; i < GRU_NODES * DD / 4; i += GRU_THREADS)
        ((float4*)s_x)[i] = ((const float4*)g_msg)[base * (DD / 4) + i];
    for (int i = tid; i < TD; i += GRU_THREADS) { s_bi[i] = bih[i]; s_bh[i] = bhh[i]; }
    __syncthreads();

    if (act) {
        float4 br = *(const float4*)&s_bi[k0];
        float4 bz = *(const float4*)&s_bi[DD + k0];
        float4 bn = *(const float4*)&s_bi[2 * DD + k0];
        u64 aR[8][2], aZ[8][2], aN[8][2];
#pragma unroll
        for (int nn = 0; nn < 8; nn++) {
            aR[nn][0] = pk2(br.x, br.y); aR[nn][1] = pk2(br.z, br.w);
            aZ[nn][0] = pk2(bz.x, bz.y); aZ[nn][1] = pk2(bz.z, bz.w);
            aN[nn][0] = pk2(bn.x, bn.y); aN[nn][1] = pk2(bn.z, bn.w);
        }
        const float* xp = s_x + nb * DD;
#pragma unroll 2
        for (int d = 0; d < DD; d++) {
            const float* wrow = s_w + d * TD + k0;
            ulonglong2 wr = *(const ulonglong2*)(wrow);
            ulonglong2 wz = *(const ulonglong2*)(wrow + DD);
            ulonglong2 wn = *(const ulonglong2*)(wrow + 2 * DD);
#pragma unroll
            for (int nn = 0; nn < 8; nn++) {
                u64 v = dup2(xp[nn * DD + d]);
                aR[nn][0] = ffma2(wr.x, v, aR[nn][0]); aR[nn][1] = ffma2(wr.y, v, aR[nn][1]);
                aZ[nn][0] = ffma2(wz.x, v, aZ[nn][0]); aZ[nn][1] = ffma2(wz.y, v, aZ[nn][1]);
                aN[nn][0] = ffma2(wn.x, v, aN[nn][0]); aN[nn][1] = ffma2(wn.y, v, aN[nn][1]);
            }
        }
#pragma unroll
        for (int nn = 0; nn < 8; nn++) {
            float* g = s_gi + (nb + nn) * TD;
            *(ulonglong2*)&g[k0]          = make_ulonglong2(aR[nn][0], aR[nn][1]);
            *(ulonglong2*)&g[DD + k0]     = make_ulonglong2(aZ[nn][0], aZ[nn][1]);
            *(ulonglong2*)&g[2 * DD + k0] = make_ulonglong2(aN[nn][0], aN[nn][1]);
        }
    }
    __syncthreads();

    // ---- phase 2: Whh + h tile ----
    for (int i = tid; i < 7500; i += GRU_THREADS)
        ((float4*)s_w)[i] = ((const float4*)WThh)[i];
    for (int i = tid; i < GRU_NODES * DD / 4; i += GRU_THREADS)
        ((float4*)s_x)[i] = ((const float4*)g_h)[base * (DD / 4) + i];
    __syncthreads();

    if (act) {
        float4 br = *(const float4*)&s_bh[k0];
        float4 bz = *(const float4*)&s_bh[DD + k0];
        float4 bn = *(const float4*)&s_bh[2 * DD + k0];
        u64 aR[8][2], aZ[8][2], aN[8][2];
#pragma unroll
        for (int nn = 0; nn < 8; nn++) {
            aR[nn][0] = pk2(br.x, br.y); aR[nn][1] = pk2(br.z, br.w);
            aZ[nn][0] = pk2(bz.x, bz.y); aZ[nn][1] = pk2(bz.z, bz.w);
            aN[nn][0] = pk2(bn.x, bn.y); aN[nn][1] = pk2(bn.z, bn.w);
        }
        const float* hp = s_x + nb * DD;
#pragma unroll 2
        for (int d = 0; d < DD; d++) {
            const float* wrow = s_w + d * TD + k0;
            ulonglong2 wr = *(const ulonglong2*)(wrow);
            ulonglong2 wz = *(const ulonglong2*)(wrow + DD);
            ulonglong2 wn = *(const ulonglong2*)(wrow + 2 * DD);
#pragma unroll
            for (int nn = 0; nn < 8; nn++) {
                u64 v = dup2(hp[nn * DD + d]);
                aR[nn][0] = ffma2(wr.x, v, aR[nn][0]); aR[nn][1] = ffma2(wr.y, v, aR[nn][1]);
                aZ[nn][0] = ffma2(wz.x, v, aZ[nn][0]); aZ[nn][1] = ffma2(wz.y, v, aZ[nn][1]);
                aN[nn][0] = ffma2(wn.x, v, aN[nn][0]); aN[nn][1] = ffma2(wn.y, v, aN[nn][1]);
            }
        }
        // gate fusion + state update
#pragma unroll
        for (int nn = 0; nn < 8; nn++) {
            float2 hr0 = unpk(aR[nn][0]), hr1 = unpk(aR[nn][1]);
            float2 hz0 = unpk(aZ[nn][0]), hz1 = unpk(aZ[nn][1]);
            float2 hn0 = unpk(aN[nn][0]), hn1 = unpk(aN[nn][1]);
            const float* g = s_gi + (nb + nn) * TD;
            float4 gr = *(const float4*)&g[k0];
            float4 gz = *(const float4*)&g[DD + k0];
            float4 gn = *(const float4*)&g[2 * DD + k0];
            float4 hpv = *(const float4*)&s_x[(nb + nn) * DD + k0];

            float r0 = sigf(gr.x + hr0.x), r1 = sigf(gr.y + hr0.y);
            float r2 = sigf(gr.z + hr1.x), r3 = sigf(gr.w + hr1.y);
            float z0 = sigf(gz.x + hz0.x), z1 = sigf(gz.y + hz0.y);
            float z2 = sigf(gz.z + hz1.x), z3 = sigf(gz.w + hz1.y);
            float n0 = tanhf(gn.x + r0 * hn0.x), n1 = tanhf(gn.y + r1 * hn0.y);
            float n2 = tanhf(gn.z + r2 * hn1.x), n3 = tanhf(gn.w + r3 * hn1.y);
            float4 o;
            o.x = (1.f - z0) * n0 + z0 * hpv.x;
            o.y = (1.f - z1) * n1 + z1 * hpv.y;
            o.z = (1.f - z2) * n2 + z2 * hpv.z;
            o.w = (1.f - z3) * n3 + z3 * hpv.w;
            *(float4*)&g_h[(base + nb + nn) * DD + k0] = o;
        }
    }
}

// ---------------- classifier: out = relu(h@W1+b1)@W2+b2 ----------------
__global__ void cls_kernel(const float* __restrict__ W1, const float* __restrict__ b1,
                           const float* __restrict__ W2, const float* __restrict__ b2,
                           float* __restrict__ out) {
    __shared__ float s_w1[DD * DC];
    __shared__ float s_b1[DC];
    __shared__ float s_w2[DC];
    __shared__ float s_row[8 * DD];

    int tid = threadIdx.x;
    int warp = tid >> 5, lane = tid & 31;
    int node = blockIdx.x * 8 + warp;

    for (int i = tid; i < DD * DC; i += blockDim.x) s_w1[i] = W1[i];
    if (tid < DC) { s_b1[tid] = b1[tid]; s_w2[tid] = W2[tid]; }
    __syncthreads();

    const float* hrow = &g_h[node * DD];
    float* rbuf = &s_row[warp * DD];
    rbuf[lane] = hrow[lane];
    rbuf[lane + 32] = hrow[lane + 32];
    rbuf[lane + 64] = hrow[lane + 64];
    if (lane < 4) rbuf[lane + 96] = hrow[lane + 96];
    __syncwarp();

    float v = 0.f;
    if (lane < DC) {
        float acc = s_b1[lane];
#pragma unroll 4
        for (int d = 0; d < DD; d++) acc += rbuf[d] * s_w1[d * DC + lane];
        v = fmaxf(acc, 0.f) * s_w2[lane];
    }
#pragma unroll
    for (int off = 16; off > 0; off >>= 1) v += __shfl_down_sync(0xFFFFFFFFu, v, off);
    if (lane == 0) out[node] = v + b2[0];
}

// ---------------- host launch ----------------
extern "C" void kernel_launch(void* const* d_in, const int* in_sizes, int n_in,
                              void* d_out, int out_size) {
    const float* features = (const float*)d_in[0];
    const int* edge_row   = (const int*)d_in[1];
    const int* edge_col   = (const int*)d_in[2];
    const float* init_W = (const float*)d_in[3];
    const float* init_b = (const float*)d_in[4];
    const float* fmsg_W1 = (const float*)d_in[5];
    const float* fmsg_b1 = (const float*)d_in[6];
    const float* fmsg_W2 = (const float*)d_in[7];
    const float* fmsg_b2 = (const float*)d_in[8];
    const float* bmsg_W1 = (const float*)d_in[9];
    const float* bmsg_b1 = (const float*)d_in[10];
    const float* bmsg_W2 = (const float*)d_in[11];
    const float* bmsg_b2 = (const float*)d_in[12];
    const float* fgru_Wih = (const float*)d_in[13];
    const float* fgru_Whh = (const float*)d_in[14];
    const float* fgru_bih = (const float*)d_in[15];
    const float* fgru_bhh = (const float*)d_in[16];
    const float* bgru_Wih = (const float*)d_in[17];
    const float* bgru_Whh = (const float*)d_in[18];
    const float* bgru_bih = (const float*)d_in[19];
    const float* bgru_bhh = (const float*)d_in[20];
    const float* cls_W1 = (const float*)d_in[21];
    const float* cls_b1 = (const float*)d_in[22];
    const float* cls_W2 = (const float*)d_in[23];
    const float* cls_b2 = (const float*)d_in[24];
    float* out = (float*)d_out;

    const int mlp_smem = MLP_SMEM_FLOATS * 4;
    const int gru_smem = GRU_SMEM_FLOATS * 4;
    cudaFuncSetAttribute((const void*)mlp_kernel,
                         cudaFuncAttributeMaxDynamicSharedMemorySize, mlp_smem);
    cudaFuncSetAttribute((const void*)gru_kernel,
                         cudaFuncAttributeMaxDynamicSharedMemorySize, gru_smem);

    // resolve pre-transposed weight scratch base
    float* wt_base = nullptr;
    cudaGetSymbolAddress((void**)&wt_base, g_WT);
    const float* fWihT = wt_base;
    const float* fWhhT = wt_base + 30000;
    const float* bWihT = wt_base + 60000;
    const float* bWhhT = wt_base + 90000;

    init_kernel<<<(ND + 255) / 256, 256>>>(features, init_W, init_b);
    transpose_w_kernel<<<(30000 + 255) / 256, 256>>>(fgru_Wih, fgru_Whh, bgru_Wih, bgru_Whh);

    const int mlp_blocks = NN / MLP_NODES;      // 2048
    const int gru_blocks = NN / GRU_NODES;      // 2048
    const int zero_blocks = (ND / 4) / 256;     // 12800
    const int scat_blocks = EE / 8;             // 65536 (8 warps/block, warp per edge)

    for (int r = 0; r < 20; r++) {
        // forward pass
        mlp_kernel<<<mlp_blocks, MLP_THREADS, mlp_smem>>>(fmsg_W1, fmsg_b1, fmsg_W2, fmsg_b2);
        zero_kernel<<<zero_blocks, 256>>>();
        scatter_kernel<<<scat_blocks, 256>>>(edge_col, edge_row);   // msg[row] += fm[col]
        gru_kernel<<<gru_blocks, GRU_THREADS, gru_smem>>>(fWihT, fWhhT, fgru_bih, fgru_bhh);
        // backward pass
        mlp_kernel<<<mlp_blocks, MLP_THREADS, mlp_smem>>>(bmsg_W1, bmsg_b1, bmsg_W2, bmsg_b2);
        zero_kernel<<<zero_blocks, 256>>>();
        scatter_kernel<<<scat_blocks, 256>>>(edge_row, edge_col);   // msg[col] += bm[row]
        gru_kernel<<<gru_blocks, GRU_THREADS, gru_smem>>>(bWihT, bWhhT, bgru_bih, bgru_bhh);
    }

    cls_kernel<<<NN / 8, 256>>>(cls_W1, cls_b1, cls_W2, cls_b2, out);
    (void)in_sizes; (void)n_in; (void)out_size;
}

// round 5
// speedup vs baseline: 1.2346x; 1.0853x over previous
#include <cuda_runtime.h>
#include <cuda_bf16.h>

// ---------------- problem constants ----------------
#define NN 131072
#define EE 524288
#define DD 100
#define TD 300
#define DA 50
#define DC 30
#define ND (NN*DD)          // 13,107,200

// ---------------- scratch (static device globals; no allocation) ----------------
__device__ float g_h[ND];
__device__ float g_fm[ND];
__device__ float g_msg[ND];
__device__ float g_WT[4][30000];   // pre-transposed [d][j] GRU weights

// CSR scratch (edges are constant -> build once per launch)
__device__ int g_degF[NN], g_degB[NN];
__device__ int g_rpF[NN], g_rpB[NN];
__device__ int g_fillF[NN], g_fillB[NN];
__device__ int g_eF[EE], g_eB[EE];
__device__ int g_bsum[256];

// ---------------- f32x2 packed-FMA helpers (sm_103a FFMA2 path) ----------------
typedef unsigned long long u64;

__device__ __forceinline__ u64 ffma2(u64 a, u64 b, u64 c) {
    u64 d;
    asm("fma.rn.f32x2 %0, %1, %2, %3;" : "=l"(d) : "l"(a), "l"(b), "l"(c));
    return d;
}
__device__ __forceinline__ u64 dup2(float x) {
    u64 d;
    asm("mov.b64 %0, {%1, %1};" : "=l"(d) : "f"(x));
    return d;
}
__device__ __forceinline__ u64 pk2(float a, float b) {
    u64 d;
    asm("mov.b64 %0, {%1, %2};" : "=l"(d) : "f"(a), "f"(b));
    return d;
}
__device__ __forceinline__ float2 unpk(u64 a) {
    float2 r;
    asm("mov.b64 {%0, %1}, %2;" : "=f"(r.x), "=f"(r.y) : "l"(a));
    return r;
}
__device__ __forceinline__ float sigf(float v) {
    return 1.0f / (1.0f + __expf(-v));
}

// ---------------- init: h = features @ init_W + init_b ----------------
__global__ void init_kernel(const float* __restrict__ feat,
                            const float* __restrict__ W,
                            const float* __restrict__ b) {
    int i = blockIdx.x * blockDim.x + threadIdx.x;
    if (i >= ND) return;
    int n = i / DD;
    int d = i - n * DD;
    float f0 = feat[n * 4 + 0], f1 = feat[n * 4 + 1];
    float f2 = feat[n * 4 + 2], f3 = feat[n * 4 + 3];
    g_h[i] = b[d] + f0 * W[d] + f1 * W[DD + d] + f2 * W[2 * DD + d] + f3 * W[3 * DD + d];
}

// ---------------- one-time weight transpose ----------------
__global__ void transpose_w_kernel(const float* __restrict__ A, const float* __restrict__ B,
                                   const float* __restrict__ C, const float* __restrict__ E) {
    int i = blockIdx.x * blockDim.x + threadIdx.x;
    if (i >= 30000) return;
    int d = i / TD, j = i - d * TD;
    int src = j * DD + d;
    g_WT[0][i] = A[src];
    g_WT[1][i] = B[src];
    g_WT[2][i] = C[src];
    g_WT[3][i] = E[src];
}

// ---------------- CSR build kernels ----------------
__global__ void zero_deg_kernel() {
    int i = blockIdx.x * blockDim.x + threadIdx.x;
    g_degF[i] = 0;
    g_degB[i] = 0;
}
__global__ void count_deg_kernel(const int* __restrict__ row, const int* __restrict__ col) {
    int e = blockIdx.x * blockDim.x + threadIdx.x;
    atomicAdd(&g_degF[row[e]], 1);
    atomicAdd(&g_degB[col[e]], 1);
}
__global__ void scan1_kernel() {   // grid 256: blocks 0..127 -> F, 128..255 -> B
    __shared__ int s[1024];
    int b = blockIdx.x;
    const int* deg = (b < 128) ? g_degF : g_degB;
    int* rp = (b < 128) ? g_rpF : g_rpB;
    int base = (b & 127) * 1024;
    for (int i = threadIdx.x; i < 1024; i += blockDim.x) s[i] = deg[base + i];
    __syncthreads();
    if (threadIdx.x == 0) {
        int run = 0;
        for (int i = 0; i < 1024; i++) { int v = s[i]; s[i] = run; run += v; }
        g_bsum[b] = run;
    }
    __syncthreads();
    for (int i = threadIdx.x; i < 1024; i += blockDim.x) rp[base + i] = s[i];
}
__global__ void scan2_kernel() {   // <<<1,2>>>: t0 scans F block sums, t1 B
    int t = threadIdx.x;
    int base = t * 128;
    int run = 0;
    for (int i = 0; i < 128; i++) { int v = g_bsum[base + i]; g_bsum[base + i] = run; run += v; }
}
__global__ void scan3_kernel() {   // grid (2*NN)/256: add block offsets, copy fill cursors
    int i = blockIdx.x * blockDim.x + threadIdx.x;
    if (i < NN) {
        int v = g_rpF[i] + g_bsum[i >> 10];
        g_rpF[i] = v; g_fillF[i] = v;
    } else {
        int j = i - NN;
        int v = g_rpB[j] + g_bsum[128 + (j >> 10)];
        g_rpB[j] = v; g_fillB[j] = v;
    }
}
__global__ void fill_csr_kernel(const int* __restrict__ row, const int* __restrict__ col) {
    int e = blockIdx.x * blockDim.x + threadIdx.x;
    int r = row[e], c = col[e];
    int pF = atomicAdd(&g_fillF[r], 1);
    g_eF[pF] = c;
    int pB = atomicAdd(&g_fillB[c], 1);
    g_eB[pB] = r;
}

// ---------------- gather: msg[n] = sum_{e in csr[n]} fm[eidx[e]] ----------------
__global__ void gather_kernel(const int* __restrict__ rp, const int* __restrict__ deg,
                              const int* __restrict__ eidx) {
    int node = (blockIdx.x * blockDim.x + threadIdx.x) >> 5;
    int lane = threadIdx.x & 31;
    if (lane >= 25) return;
    int s0 = rp[node];
    int cnt = deg[node];
    float4 acc = make_float4(0.f, 0.f, 0.f, 0.f);
    for (int i = 0; i < cnt; i++) {
        int s = eidx[s0 + i];
        float4 v = *(const float4*)&g_fm[s * DD + 4 * lane];
        acc.x += v.x; acc.y += v.y; acc.z += v.z; acc.w += v.w;
    }
    *(float4*)&g_msg[node * DD + 4 * lane] = acc;
}

// ---------------- fused 2-layer message MLP (8 nodes/warp, float4 x bcast) ----------------
#define MLP_THREADS 256
#define MLP_NODES 64
#define HID 52   // DA padded to 52 (zeros in cols 50,51) for uniform float4 loops
#define MLP_SMEM_FLOATS (5000 + HID*DD + MLP_NODES*DD + MLP_NODES*HID + DD + 64)
// s_w1[5000] s_w2[5200] s_h[6400] s_hid[3328] s_b2[100] s_b1[..]

__global__ void __launch_bounds__(MLP_THREADS, 2)
mlp_kernel(const float* __restrict__ W1, const float* __restrict__ b1,
           const float* __restrict__ W2, const float* __restrict__ b2) {
    extern __shared__ float smem[];
    float* s_w1 = smem;
    float* s_w2 = s_w1 + 5000;
    float* s_h  = s_w2 + HID * DD;
    float* s_hid = s_h + MLP_NODES * DD;
    float* s_b2 = s_hid + MLP_NODES * HID;
    float* s_b1 = s_b2 + DD;

    int tid = threadIdx.x;
    int base = blockIdx.x * MLP_NODES;

    for (int i = tid; i < 5000; i += MLP_THREADS) s_w1[i] = W1[i];
    for (int i = tid; i < HID * DD; i += MLP_THREADS) s_w2[i] = (i < 5000) ? W2[i] : 0.f;
    for (int i = tid; i < MLP_NODES * DD / 4; i += MLP_THREADS)
        ((float4*)s_h)[i] = ((const float4*)g_h)[base * (DD / 4) + i];
    if (tid < DD) s_b2[tid] = b2[tid];
    if (tid < DA) s_b1[tid] = b1[tid];
    __syncthreads();

    int warp = tid >> 5, lane = tid & 31;
    int nb = warp * 8;
    int k0 = 4 * lane;
    bool act = lane < 25;

    // layer 1: hidden[2*lane], hidden[2*lane+1]
    if (act) {
        int j0 = 2 * lane;
        u64 bias = pk2(s_b1[j0], s_b1[j0 + 1]);
        u64 acc[8];
#pragma unroll
        for (int nn = 0; nn < 8; nn++) acc[nn] = bias;
        const float* xp = s_h + nb * DD;
#pragma unroll 1
        for (int d4 = 0; d4 < DD; d4 += 4) {
            float4 xv[8];
#pragma unroll
            for (int nn = 0; nn < 8; nn++) xv[nn] = *(const float4*)&xp[nn * DD + d4];
#pragma unroll
            for (int dd = 0; dd < 4; dd++) {
                u64 w = *(const u64*)&s_w1[(d4 + dd) * DA + j0];
#pragma unroll
                for (int nn = 0; nn < 8; nn++)
                    acc[nn] = ffma2(w, dup2(((const float*)&xv[nn])[dd]), acc[nn]);
            }
        }
#pragma unroll
        for (int nn = 0; nn < 8; nn++) {
            float2 v = unpk(acc[nn]);
            *(float2*)&s_hid[(nb + nn) * HID + j0] =
                make_float2(fmaxf(v.x, 0.f), fmaxf(v.y, 0.f));
        }
    } else if (lane == 25) {
        // zero the padded cols 50,51
#pragma unroll
        for (int nn = 0; nn < 8; nn++)
            *(float2*)&s_hid[(nb + nn) * HID + 50] = make_float2(0.f, 0.f);
    }
    __syncwarp();

    // layer 2: out[k0..k0+3]
    if (act) {
        float4 bb = *(const float4*)&s_b2[k0];
        u64 a[8][2];
#pragma unroll
        for (int nn = 0; nn < 8; nn++) { a[nn][0] = pk2(bb.x, bb.y); a[nn][1] = pk2(bb.z, bb.w); }
        const float* hp = s_hid + nb * HID;
#pragma unroll 1
        for (int j4 = 0; j4 < HID; j4 += 4) {
            float4 hv[8];
#pragma unroll
            for (int nn = 0; nn < 8; nn++) hv[nn] = *(const float4*)&hp[nn * HID + j4];
#pragma unroll
            for (int dd = 0; dd < 4; dd++) {
                ulonglong2 w = *(const ulonglong2*)&s_w2[(j4 + dd) * DD + k0];
#pragma unroll
                for (int nn = 0; nn < 8; nn++) {
                    u64 v = dup2(((const float*)&hv[nn])[dd]);
                    a[nn][0] = ffma2(w.x, v, a[nn][0]);
                    a[nn][1] = ffma2(w.y, v, a[nn][1]);
                }
            }
        }
#pragma unroll
        for (int nn = 0; nn < 8; nn++) {
            float2 p0 = unpk(a[nn][0]), p1 = unpk(a[nn][1]);
            *(float4*)&g_fm[(base + nb + nn) * DD + k0] =
                make_float4(p0.x, p0.y, p1.x, p1.y);
        }
    }
}

// ---------------- fused GRU step (8 nodes/warp, float4 x bcast) ----------------
#define GRU_THREADS 256
#define GRU_NODES 64
#define GRU_SMEM_FLOATS (30000 + GRU_NODES*TD + GRU_NODES*DD + 300 + 300)

__global__ void __launch_bounds__(GRU_THREADS, 1)
gru_kernel(const float* __restrict__ WTih, const float* __restrict__ WThh,
           const float* __restrict__ bih, const float* __restrict__ bhh) {
    extern __shared__ float smem[];
    float* s_w  = smem;
    float* s_gi = s_w + 30000;
    float* s_x  = s_gi + GRU_NODES * TD;
    float* s_bi = s_x + GRU_NODES * DD;
    float* s_bh = s_bi + TD;

    int tid = threadIdx.x;
    int base = blockIdx.x * GRU_NODES;
    int warp = tid >> 5, lane = tid & 31;
    int nb = warp * 8;
    int k0 = 4 * lane;
    bool act = lane < 25;

    // ---- phase 1: Wih^T + msg tile ----
    for (int i = tid; i < 7500; i += GRU_THREADS)
        ((float4*)s_w)[i] = ((const float4*)WTih)[i];
    for (int i = tid; i < GRU_NODES * DD / 4; i += GRU_THREADS)
        ((float4*)s_x)[i] = ((const float4*)g_msg)[base * (DD / 4) + i];
    for (int i = tid; i < TD; i += GRU_THREADS) { s_bi[i] = bih[i]; s_bh[i] = bhh[i]; }
    __syncthreads();

    if (act) {
        float4 br = *(const float4*)&s_bi[k0];
        float4 bz = *(const float4*)&s_bi[DD + k0];
        float4 bn = *(const float4*)&s_bi[2 * DD + k0];
        u64 aR[8][2], aZ[8][2], aN[8][2];
#pragma unroll
        for (int nn = 0; nn < 8; nn++) {
            aR[nn][0] = pk2(br.x, br.y); aR[nn][1] = pk2(br.z, br.w);
            aZ[nn][0] = pk2(bz.x, bz.y); aZ[nn][1] = pk2(bz.z, bz.w);
            aN[nn][0] = pk2(bn.x, bn.y); aN[nn][1] = pk2(bn.z, bn.w);
        }
        const float* xp = s_x + nb * DD;
#pragma unroll 1
        for (int d4 = 0; d4 < DD; d4 += 4) {
            float4 xv[8];
#pragma unroll
            for (int nn = 0; nn < 8; nn++) xv[nn] = *(const float4*)&xp[nn * DD + d4];
#pragma unroll
            for (int dd = 0; dd < 4; dd++) {
                const float* wrow = s_w + (d4 + dd) * TD + k0;
                ulonglong2 wr = *(const ulonglong2*)(wrow);
                ulonglong2 wz = *(const ulonglong2*)(wrow + DD);
                ulonglong2 wn = *(const ulonglong2*)(wrow + 2 * DD);
#pragma unroll
                for (int nn = 0; nn < 8; nn++) {
                    u64 v = dup2(((const float*)&xv[nn])[dd]);
                    aR[nn][0] = ffma2(wr.x, v, aR[nn][0]); aR[nn][1] = ffma2(wr.y, v, aR[nn][1]);
                    aZ[nn][0] = ffma2(wz.x, v, aZ[nn][0]); aZ[nn][1] = ffma2(wz.y, v, aZ[nn][1]);
                    aN[nn][0] = ffma2(wn.x, v, aN[nn][0]); aN[nn][1] = ffma2(wn.y, v, aN[nn][1]);
                }
            }
        }
#pragma unroll
        for (int nn = 0; nn < 8; nn++) {
            float* g = s_gi + (nb + nn) * TD;
            *(ulonglong2*)&g[k0]          = make_ulonglong2(aR[nn][0], aR[nn][1]);
            *(ulonglong2*)&g[DD + k0]     = make_ulonglong2(aZ[nn][0], aZ[nn][1]);
            *(ulonglong2*)&g[2 * DD + k0] = make_ulonglong2(aN[nn][0], aN[nn][1]);
        }
    }
    __syncthreads();

    // ---- phase 2: Whh^T + h tile ----
    for (int i = tid; i < 7500; i += GRU_THREADS)
        ((float4*)s_w)[i] = ((const float4*)WThh)[i];
    for (int i = tid; i < GRU_NODES * DD / 4; i += GRU_THREADS)
        ((float4*)s_x)[i] = ((const float4*)g_h)[base * (DD / 4) + i];
    __syncthreads();

    if (act) {
        float4 br = *(const float4*)&s_bh[k0];
        float4 bz = *(const float4*)&s_bh[DD + k0];
        float4 bn = *(const float4*)&s_bh[2 * DD + k0];
        u64 aR[8][2], aZ[8][2], aN[8][2];
#pragma unroll
        for (int nn = 0; nn < 8; nn++) {
            aR[nn][0] = pk2(br.x, br.y); aR[nn][1] = pk2(br.z, br.w);
            aZ[nn][0] = pk2(bz.x, bz.y); aZ[nn][1] = pk2(bz.z, bz.w);
            aN[nn][0] = pk2(bn.x, bn.y); aN[nn][1] = pk2(bn.z, bn.w);
        }
        const float* hp = s_x + nb * DD;
#pragma unroll 1
        for (int d4 = 0; d4 < DD; d4 += 4) {
            float4 xv[8];
#pragma unroll
            for (int nn = 0; nn < 8; nn++) xv[nn] = *(const float4*)&hp[nn * DD + d4];
#pragma unroll
            for (int dd = 0; dd < 4; dd++) {
                const float* wrow = s_w + (d4 + dd) * TD + k0;
                ulonglong2 wr = *(const ulonglong2*)(wrow);
                ulonglong2 wz = *(const ulonglong2*)(wrow + DD);
                ulonglong2 wn = *(const ulonglong2*)(wrow + 2 * DD);
#pragma unroll
                for (int nn = 0; nn < 8; nn++) {
                    u64 v = dup2(((const float*)&xv[nn])[dd]);
                    aR[nn][0] = ffma2(wr.x, v, aR[nn][0]); aR[nn][1] = ffma2(wr.y, v, aR[nn][1]);
                    aZ[nn][0] = ffma2(wz.x, v, aZ[nn][0]); aZ[nn][1] = ffma2(wz.y, v, aZ[nn][1]);
                    aN[nn][0] = ffma2(wn.x, v, aN[nn][0]); aN[nn][1] = ffma2(wn.y, v, aN[nn][1]);
                }
            }
        }
        // gate fusion + state update
#pragma unroll
        for (int nn = 0; nn < 8; nn++) {
            float2 hr0 = unpk(aR[nn][0]), hr1 = unpk(aR[nn][1]);
            float2 hz0 = unpk(aZ[nn][0]), hz1 = unpk(aZ[nn][1]);
            float2 hn0 = unpk(aN[nn][0]), hn1 = unpk(aN[nn][1]);
            const float* g = s_gi + (nb + nn) * TD;
            float4 gr = *(const float4*)&g[k0];
            float4 gz = *(const float4*)&g[DD + k0];
            float4 gn = *(const float4*)&g[2 * DD + k0];
            float4 hpv = *(const float4*)&s_x[(nb + nn) * DD + k0];

            float r0 = sigf(gr.x + hr0.x), r1 = sigf(gr.y + hr0.y);
            float r2 = sigf(gr.z + hr1.x), r3 = sigf(gr.w + hr1.y);
            float z0 = sigf(gz.x + hz0.x), z1 = sigf(gz.y + hz0.y);
            float z2 = sigf(gz.z + hz1.x), z3 = sigf(gz.w + hz1.y);
            float n0 = tanhf(gn.x + r0 * hn0.x), n1 = tanhf(gn.y + r1 * hn0.y);
            float n2 = tanhf(gn.z + r2 * hn1.x), n3 = tanhf(gn.w + r3 * hn1.y);
            float4 o;
            o.x = (1.f - z0) * n0 + z0 * hpv.x;
            o.y = (1.f - z1) * n1 + z1 * hpv.y;
            o.z = (1.f - z2) * n2 + z2 * hpv.z;
            o.w = (1.f - z3) * n3 + z3 * hpv.w;
            *(float4*)&g_h[(base + nb + nn) * DD + k0] = o;
        }
    }
}

// ---------------- classifier ----------------
__global__ void cls_kernel(const float* __restrict__ W1, const float* __restrict__ b1,
                           const float* __restrict__ W2, const float* __restrict__ b2,
                           float* __restrict__ out) {
    __shared__ float s_w1[DD * DC];
    __shared__ float s_b1[DC];
    __shared__ float s_w2[DC];
    __shared__ float s_row[8 * DD];

    int tid = threadIdx.x;
    int warp = tid >> 5, lane = tid & 31;
    int node = blockIdx.x * 8 + warp;

    for (int i = tid; i < DD * DC; i += blockDim.x) s_w1[i] = W1[i];
    if (tid < DC) { s_b1[tid] = b1[tid]; s_w2[tid] = W2[tid]; }
    __syncthreads();

    const float* hrow = &g_h[node * DD];
    float* rbuf = &s_row[warp * DD];
    rbuf[lane] = hrow[lane];
    rbuf[lane + 32] = hrow[lane + 32];
    rbuf[lane + 64] = hrow[lane + 64];
    if (lane < 4) rbuf[lane + 96] = hrow[lane + 96];
    __syncwarp();

    float v = 0.f;
    if (lane < DC) {
        float acc = s_b1[lane];
#pragma unroll 4
        for (int d = 0; d < DD; d++) acc += rbuf[d] * s_w1[d * DC + lane];
        v = fmaxf(acc, 0.f) * s_w2[lane];
    }
#pragma unroll
    for (int off = 16; off > 0; off >>= 1) v += __shfl_down_sync(0xFFFFFFFFu, v, off);
    if (lane == 0) out[node] = v + b2[0];
}

// ---------------- host launch ----------------
extern "C" void kernel_launch(void* const* d_in, const int* in_sizes, int n_in,
                              void* d_out, int out_size) {
    const float* features = (const float*)d_in[0];
    const int* edge_row   = (const int*)d_in[1];
    const int* edge_col   = (const int*)d_in[2];
    const float* init_W = (const float*)d_in[3];
    const float* init_b = (const float*)d_in[4];
    const float* fmsg_W1 = (const float*)d_in[5];
    const float* fmsg_b1 = (const float*)d_in[6];
    const float* fmsg_W2 = (const float*)d_in[7];
    const float* fmsg_b2 = (const float*)d_in[8];
    const float* bmsg_W1 = (const float*)d_in[9];
    const float* bmsg_b1 = (const float*)d_in[10];
    const float* bmsg_W2 = (const float*)d_in[11];
    const float* bmsg_b2 = (const float*)d_in[12];
    const float* fgru_Wih = (const float*)d_in[13];
    const float* fgru_Whh = (const float*)d_in[14];
    const float* fgru_bih = (const float*)d_in[15];
    const float* fgru_bhh = (const float*)d_in[16];
    const float* bgru_Wih = (const float*)d_in[17];
    const float* bgru_Whh = (const float*)d_in[18];
    const float* bgru_bih = (const float*)d_in[19];
    const float* bgru_bhh = (const float*)d_in[20];
    const float* cls_W1 = (const float*)d_in[21];
    const float* cls_b1 = (const float*)d_in[22];
    const float* cls_W2 = (const float*)d_in[23];
    const float* cls_b2 = (const float*)d_in[24];
    float* out = (float*)d_out;

    const int mlp_smem = MLP_SMEM_FLOATS * 4;
    const int gru_smem = GRU_SMEM_FLOATS * 4;
    cudaFuncSetAttribute((const void*)mlp_kernel,
                         cudaFuncAttributeMaxDynamicSharedMemorySize, mlp_smem);
    cudaFuncSetAttribute((const void*)gru_kernel,
                         cudaFuncAttributeMaxDynamicSharedMemorySize, gru_smem);

    // resolve device-global scratch addresses
    float* wt_base = nullptr;
    cudaGetSymbolAddress((void**)&wt_base, g_WT);
    const float* fWihT = wt_base;
    const float* fWhhT = wt_base + 30000;
    const float* bWihT = wt_base + 60000;
    const float* bWhhT = wt_base + 90000;
    int *rpF, *rpB, *degF, *degB, *eF, *eB;
    cudaGetSymbolAddress((void**)&rpF, g_rpF);
    cudaGetSymbolAddress((void**)&rpB, g_rpB);
    cudaGetSymbolAddress((void**)&degF, g_degF);
    cudaGetSymbolAddress((void**)&degB, g_degB);
    cudaGetSymbolAddress((void**)&eF, g_eF);
    cudaGetSymbolAddress((void**)&eB, g_eB);

    init_kernel<<<(ND + 255) / 256, 256>>>(features, init_W, init_b);
    transpose_w_kernel<<<(30000 + 255) / 256, 256>>>(fgru_Wih, fgru_Whh, bgru_Wih, bgru_Whh);

    // CSR build (edges constant across rounds)
    zero_deg_kernel<<<NN / 256, 256>>>();
    count_deg_kernel<<<EE / 256, 256>>>(edge_row, edge_col);
    scan1_kernel<<<256, 256>>>();
    scan2_kernel<<<1, 2>>>();
    scan3_kernel<<<(2 * NN) / 256, 256>>>();
    fill_csr_kernel<<<EE / 256, 256>>>(edge_row, edge_col);

    const int mlp_blocks = NN / MLP_NODES;      // 2048
    const int gru_blocks = NN / GRU_NODES;      // 2048
    const int gat_blocks = NN / 8;              // 16384 (warp per node)

    for (int r = 0; r < 20; r++) {
        // forward: msg[row] = sum fm[col]
        mlp_kernel<<<mlp_blocks, MLP_THREADS, mlp_smem>>>(fmsg_W1, fmsg_b1, fmsg_W2, fmsg_b2);
        gather_kernel<<<gat_blocks, 256>>>(rpF, degF, eF);
        gru_kernel<<<gru_blocks, GRU_THREADS, gru_smem>>>(fWihT, fWhhT, fgru_bih, fgru_bhh);
        // backward: msg[col] = sum bm[row]
        mlp_kernel<<<mlp_blocks, MLP_THREADS, mlp_smem>>>(bmsg_W1, bmsg_b1, bmsg_W2, bmsg_b2);
        gather_kernel<<<gat_blocks, 256>>>(rpB, degB, eB);
        gru_kernel<<<gru_blocks, GRU_THREADS, gru_smem>>>(bWihT, bWhhT, bgru_bih, bgru_bhh);
    }

    cls_kernel<<<NN / 8, 256>>>(cls_W1, cls_b1, cls_W2, cls_b2, out);
    (void)in_sizes; (void)n_in; (void)out_size;
}